// round 4
// baseline (speedup 1.0000x reference)
#include <cuda_runtime.h>

namespace {
constexpr int kB = 128, kS = 2048, kD = 128, kNQ = 18;
constexpr int TS = 128;                 // s-tile size
constexpr int NTILE = kS / TS;          // 16
constexpr int THREADS = 512;
constexpr float SCALE = 0.08838834764831845f;  // 1/sqrt(128)

constexpr int XBUF_F4 = TS * 32;                 // float4 per x buffer
constexpr int SMEM_X = 2 * XBUF_F4 * 16;         // 131072 B (double buffer)
constexpr int SMEM_Q = kNQ * kD * 4;             // 9216 B
constexpr int SMEM_P = kNQ * TS * 4;             // 9216 B
constexpr int SMEM_BYTES = SMEM_X + SMEM_Q + SMEM_P + 128;
constexpr int OUT_PER_B = kNQ * kD;              // 2304
}

// ---- packed f32x2 helpers (B300 FFMA2 path, only reachable via PTX) ----
__device__ __forceinline__ unsigned long long pk2(float a, float b) {
    unsigned long long r;
    asm("mov.b64 %0, {%1,%2};" : "=l"(r) : "f"(a), "f"(b));
    return r;
}
__device__ __forceinline__ unsigned long long f2ma(unsigned long long a,
                                                   unsigned long long b,
                                                   unsigned long long c) {
    unsigned long long d;
    asm("fma.rn.f32x2 %0, %1, %2, %3;" : "=l"(d) : "l"(a), "l"(b), "l"(c));
    return d;
}
__device__ __forceinline__ float2 up2(unsigned long long v) {
    float lo, hi;
    asm("mov.b64 {%0,%1}, %2;" : "=f"(lo), "=f"(hi) : "l"(v));
    return make_float2(lo, hi);
}
__device__ __forceinline__ void cpa16(void* dst, const void* src) {
    unsigned a = (unsigned)__cvta_generic_to_shared(dst);
    asm volatile("cp.async.cg.shared.global [%0], [%1], 16;" :: "r"(a), "l"(src));
}

__global__ void __launch_bounds__(THREADS, 1)
AttentionPooling_main(const float* __restrict__ x,
                      const float* __restrict__ qe,
                      const int*   __restrict__ ques,
                      const int*   __restrict__ mask,
                      float*       __restrict__ out)
{
    extern __shared__ char smem[];
    float4* xb4  = reinterpret_cast<float4*>(smem);
    float*  q_sm = reinterpret_cast<float*>(smem + SMEM_X);
    float*  p_sm = q_sm + kNQ * kD;
    float*  l_sm = p_sm + kNQ * TS;

    const int t = threadIdx.x;
    const int b = blockIdx.x;

    // ---- gather question embeddings, pre-scaled by 1/sqrt(D) ----
    // NOTE: kNQ*32 = 576 > THREADS, must be a strided loop.
    for (int i = t; i < kNQ * 32; i += THREADS) {
        int j = i >> 5, d4 = i & 31;
        int qi = ques[b * kNQ + j];
        float4 v = reinterpret_cast<const float4*>(qe + qi * kD)[d4];
        v.x *= SCALE; v.y *= SCALE; v.z *= SCALE; v.w *= SCALE;
        reinterpret_cast<float4*>(q_sm)[j * 32 + d4] = v;
    }
    if (t < kNQ) l_sm[t] = 0.0f;

    const float* xb = x + (size_t)b * kS * kD;
    const int*   mb = mask + b * kS;

    // swizzled tile store: col' = (d4 + s) & 31 -> conflict-free row & column reads
    auto load_tile = [&](int tile, int buf) {
        const float* src = xb + tile * TS * kD;
        float4* dst = xb4 + buf * XBUF_F4;
        #pragma unroll
        for (int k = 0; k < 8; ++k) {
            int i = t + k * THREADS;          // 4096 float4s
            int s = i >> 5, d4 = i & 31;
            cpa16(&dst[s * 32 + ((d4 + s) & 31)], src + s * kD + d4 * 4);
        }
        asm volatile("cp.async.commit_group;");
    };

    load_tile(0, 0);

    // phase A decomposition: bit0 = d-half, bits1..7 = s, bit8 = q-half
    const int dhA = t & 1;
    const int sA  = (t >> 1) & (TS - 1);
    const int qbA = (t >> 8) * 9;

    // phase B decomposition: bits0..4 = d4, bit5 = q-half, bits6..8 = s-slice
    const int d4B = t & 31;
    const int qbB = ((t >> 5) & 1) * 9;
    const int slB = t >> 6;                   // 0..7, 16 s each

    unsigned long long acc[9][2];
    #pragma unroll
    for (int j = 0; j < 9; ++j) { acc[j][0] = 0ull; acc[j][1] = 0ull; }

    for (int tile = 0; tile < NTILE; ++tile) {
        const int buf = tile & 1;
        if (tile + 1 < NTILE) {
            load_tile(tile + 1, buf ^ 1);
            asm volatile("cp.async.wait_group 1;");
        } else {
            asm volatile("cp.async.wait_group 0;");
        }
        __syncthreads();

        // ---- phase A: scores for 9 queries at s = sA over half of D ----
        {
            const ulonglong2* xt =
                reinterpret_cast<const ulonglong2*>(xb4 + buf * XBUF_F4 + sA * 32);
            const ulonglong2* qt = reinterpret_cast<const ulonglong2*>(q_sm);
            unsigned long long sc[9];
            #pragma unroll
            for (int j = 0; j < 9; ++j) sc[j] = 0ull;
            #pragma unroll
            for (int k = 0; k < 16; ++k) {
                const int d4 = dhA * 16 + k;
                ulonglong2 xv = xt[(d4 + sA) & 31];
                #pragma unroll
                for (int j = 0; j < 9; ++j) {
                    ulonglong2 qv = qt[(qbA + j) * 32 + d4];
                    sc[j] = f2ma(xv.x, qv.x, sc[j]);
                    sc[j] = f2ma(xv.y, qv.y, sc[j]);
                }
            }
            const int mk = mb[tile * TS + sA];
            #pragma unroll
            for (int j = 0; j < 9; ++j) {
                float2 f = up2(sc[j]);
                float sj = f.x + f.y;
                sj += __shfl_xor_sync(0xffffffffu, sj, 1);   // combine d-halves
                if (dhA == 0)
                    p_sm[(qbA + j) * TS + sA] = mk ? __expf(sj) : 0.0f;
            }
        }
        __syncthreads();

        // ---- row-sums of p into l (144 threads, smem atomics) ----
        if (t < kNQ * 8) {
            int q = t >> 3, w = t & 7;
            const float4* pr = reinterpret_cast<const float4*>(p_sm + q * TS + w * 16);
            float ss = 0.0f;
            #pragma unroll
            for (int k2 = 0; k2 < 4; ++k2) {
                float4 v = pr[k2];
                ss += (v.x + v.y) + (v.z + v.w);
            }
            atomicAdd(&l_sm[q], ss);
        }

        // ---- phase B: acc[j][4d] += p[j][s] * x[s][4d], s in 16-wide slice ----
        {
            const ulonglong2* xt =
                reinterpret_cast<const ulonglong2*>(xb4 + buf * XBUF_F4);
            #pragma unroll
            for (int i = 0; i < 4; ++i) {
                const int s0 = slB * 16 + i * 4;
                ulonglong2 xq[4];
                #pragma unroll
                for (int k2 = 0; k2 < 4; ++k2)
                    xq[k2] = xt[(s0 + k2) * 32 + ((d4B + s0 + k2) & 31)];
                #pragma unroll
                for (int j = 0; j < 9; ++j) {
                    float4 pv = reinterpret_cast<const float4*>(
                        p_sm + (qbB + j) * TS)[slB * 4 + i];
                    unsigned long long p0 = pk2(pv.x, pv.x);
                    acc[j][0] = f2ma(xq[0].x, p0, acc[j][0]);
                    acc[j][1] = f2ma(xq[0].y, p0, acc[j][1]);
                    unsigned long long p1 = pk2(pv.y, pv.y);
                    acc[j][0] = f2ma(xq[1].x, p1, acc[j][0]);
                    acc[j][1] = f2ma(xq[1].y, p1, acc[j][1]);
                    unsigned long long p2 = pk2(pv.z, pv.z);
                    acc[j][0] = f2ma(xq[2].x, p2, acc[j][0]);
                    acc[j][1] = f2ma(xq[2].y, p2, acc[j][1]);
                    unsigned long long p3 = pk2(pv.w, pv.w);
                    acc[j][0] = f2ma(xq[3].x, p3, acc[j][0]);
                    acc[j][1] = f2ma(xq[3].y, p3, acc[j][1]);
                }
            }
        }
        __syncthreads();
    }

    // ---- reduce 8 s-slices x 2 q-halves through smem (reuse x area) ----
    float* red = reinterpret_cast<float*>(smem);   // 8*18*128*4 = 73728 B
    #pragma unroll
    for (int j = 0; j < 9; ++j) {
        float2 a = up2(acc[j][0]);
        float2 c = up2(acc[j][1]);
        reinterpret_cast<float4*>(red)[(slB * kNQ + (qbB + j)) * 32 + d4B] =
            make_float4(a.x, a.y, c.x, c.y);
    }
    __syncthreads();

    float* ob = out + (size_t)b * OUT_PER_B;
    for (int o = t; o < OUT_PER_B; o += THREADS) {
        int q = o >> 7;
        float ssum = 0.0f;
        #pragma unroll
        for (int r = 0; r < 8; ++r) ssum += red[r * OUT_PER_B + o];
        ob[o] = ssum / l_sm[q];
    }
}

extern "C" void kernel_launch(void* const* d_in, const int* in_sizes, int n_in,
                              void* d_out, int out_size) {
    const float* x    = (const float*)d_in[0];
    const float* qe   = (const float*)d_in[1];
    const int*   ques = (const int*)d_in[2];
    const int*   mask = (const int*)d_in[3];
    float* out = (float*)d_out;

    cudaFuncSetAttribute(AttentionPooling_main,
                         cudaFuncAttributeMaxDynamicSharedMemorySize, SMEM_BYTES);
    AttentionPooling_main<<<kB, THREADS, SMEM_BYTES>>>(x, qe, ques, mask, out);
}

// round 5
// speedup vs baseline: 1.5309x; 1.5309x over previous
#include <cuda_runtime.h>

namespace {
constexpr int kB = 128, kS = 2048, kD = 128, kNQ = 18;
constexpr int TS = 128;                 // s-tile size
constexpr int NTILE = kS / TS;          // 16
constexpr int THREADS = 256;
constexpr float SCALE = 0.08838834764831845f;  // 1/sqrt(128)

constexpr int XBUF_F4 = TS * 32;                 // float4 per x buffer
constexpr int SMEM_X = 2 * XBUF_F4 * 16;         // 131072 B (double buffer)
constexpr int SMEM_Q = kNQ * kD * 4;             // 9216 B
constexpr int SMEM_P = kNQ * TS * 4;             // 9216 B
constexpr int SMEM_L = 128;                      // l + pad
constexpr int SMEM_M = kS * 4;                   // 8192 B mask
constexpr int SMEM_BYTES = SMEM_X + SMEM_Q + SMEM_P + SMEM_L + SMEM_M;
constexpr int OUT_PER_B = kNQ * kD;              // 2304
}

// ---- packed f32x2 helpers (B300 FFMA2 path, only reachable via PTX) ----
__device__ __forceinline__ unsigned long long pk2(float a, float b) {
    unsigned long long r;
    asm("mov.b64 %0, {%1,%2};" : "=l"(r) : "f"(a), "f"(b));
    return r;
}
__device__ __forceinline__ unsigned long long f2ma(unsigned long long a,
                                                   unsigned long long b,
                                                   unsigned long long c) {
    unsigned long long d;
    asm("fma.rn.f32x2 %0, %1, %2, %3;" : "=l"(d) : "l"(a), "l"(b), "l"(c));
    return d;
}
__device__ __forceinline__ float2 up2(unsigned long long v) {
    float lo, hi;
    asm("mov.b64 {%0,%1}, %2;" : "=f"(lo), "=f"(hi) : "l"(v));
    return make_float2(lo, hi);
}
__device__ __forceinline__ void cpa16(void* dst, const void* src) {
    unsigned a = (unsigned)__cvta_generic_to_shared(dst);
    asm volatile("cp.async.cg.shared.global [%0], [%1], 16;" :: "r"(a), "l"(src));
}

__global__ void __launch_bounds__(THREADS, 1)
AttentionPooling_main(const float* __restrict__ x,
                      const float* __restrict__ qe,
                      const int*   __restrict__ ques,
                      const int*   __restrict__ mask,
                      float*       __restrict__ out)
{
    extern __shared__ char smem[];
    float4* xb4  = reinterpret_cast<float4*>(smem);
    float*  q_sm = reinterpret_cast<float*>(smem + SMEM_X);
    float*  p_sm = q_sm + kNQ * kD;
    float*  l_sm = p_sm + kNQ * TS;
    int*    m_sm = reinterpret_cast<int*>(smem + SMEM_X + SMEM_Q + SMEM_P + SMEM_L);

    const int t = threadIdx.x;
    const int b = blockIdx.x;

    // ---- mask -> smem (once, async) ----
    {
        const int* mb = mask + b * kS;
        #pragma unroll
        for (int k = 0; k < 2; ++k) {
            int idx = t + k * THREADS;            // 512 x 16B = 8KB
            cpa16(&m_sm[idx * 4], mb + idx * 4);
        }
        asm volatile("cp.async.commit_group;");
    }

    // ---- gather question embeddings, pre-scaled by 1/sqrt(D) ----
    for (int i = t; i < kNQ * 32; i += THREADS) {
        int j = i >> 5, d4 = i & 31;
        int qi = ques[b * kNQ + j];
        float4 v = reinterpret_cast<const float4*>(qe + qi * kD)[d4];
        v.x *= SCALE; v.y *= SCALE; v.z *= SCALE; v.w *= SCALE;
        reinterpret_cast<float4*>(q_sm)[j * 32 + d4] = v;
    }
    if (t < kNQ) l_sm[t] = 0.0f;

    const float* xb = x + (size_t)b * kS * kD;

    // swizzled tile store: col' = (d4 + s) & 31
    auto load_tile = [&](int tile, int buf) {
        const float* src = xb + tile * TS * kD;
        float4* dst = xb4 + buf * XBUF_F4;
        #pragma unroll
        for (int k = 0; k < 16; ++k) {
            int i = t + k * THREADS;              // 4096 float4s
            int s = i >> 5, d4 = i & 31;
            cpa16(&dst[s * 32 + ((d4 + s) & 31)], src + s * kD + d4 * 4);
        }
        asm volatile("cp.async.commit_group;");
    };

    load_tile(0, 0);

    // ---- phase A decomposition: warp covers 32 s x 9 q x quarter-D ----
    const int w     = t >> 5, lane = t & 31;
    const int qbA   = (w >> 2) * 9;          // q-half
    const int sbA   = (w & 3) * 32;          // warp s-base
    const int dgrp  = lane >> 3;             // D quarter (0..3)
    const int sslot = lane & 7;              // s within octet
    const int srow  = sbA + sslot;           // s(si) = srow + si*8
    const int cbase = (dgrp * 8 + srow) & 31;
    const int sown  = srow + dgrp * 8;       // s owned for exp/store

    // ---- phase B decomposition: 32 d4 x 2 qh x 4 slices of 32 s ----
    const int d4B = lane;
    const int qbB = ((t >> 5) & 1) * 9;
    const int slB = t >> 6;                  // 0..3

    unsigned long long acc[9][2];
    #pragma unroll
    for (int j = 0; j < 9; ++j) { acc[j][0] = 0ull; acc[j][1] = 0ull; }

    for (int tile = 0; tile < NTILE; ++tile) {
        const int buf = tile & 1;
        if (tile + 1 < NTILE) {
            load_tile(tile + 1, buf ^ 1);
            asm volatile("cp.async.wait_group 1;");
        } else {
            asm volatile("cp.async.wait_group 0;");
        }
        __syncthreads();

        // ================= phase A =================
        {
            const ulonglong2* xt =
                reinterpret_cast<const ulonglong2*>(xb4 + buf * XBUF_F4);
            const ulonglong2* qt = reinterpret_cast<const ulonglong2*>(q_sm);

            unsigned long long sc[9][4];
            #pragma unroll
            for (int j = 0; j < 9; ++j)
                #pragma unroll
                for (int si = 0; si < 4; ++si) sc[j][si] = 0ull;

            #pragma unroll
            for (int k = 0; k < 8; ++k) {
                ulonglong2 xv[4];
                #pragma unroll
                for (int si = 0; si < 4; ++si) {
                    int c = (cbase + k + si * 8) & 31;
                    xv[si] = xt[(srow + si * 8) * 32 + c];
                }
                #pragma unroll
                for (int j = 0; j < 9; ++j) {
                    ulonglong2 qv = qt[(qbA + j) * 32 + dgrp * 8 + k];
                    #pragma unroll
                    for (int si = 0; si < 4; ++si) {
                        sc[j][si] = f2ma(xv[si].x, qv.x, sc[j][si]);
                        sc[j][si] = f2ma(xv[si].y, qv.y, sc[j][si]);
                    }
                }
            }

            const int mk = m_sm[tile * TS + sown];
            #pragma unroll
            for (int j = 0; j < 9; ++j) {
                float vs[4];
                #pragma unroll
                for (int si = 0; si < 4; ++si) {
                    float2 f = up2(sc[j][si]);
                    float v = f.x + f.y;
                    v += __shfl_xor_sync(0xffffffffu, v, 8);
                    v += __shfl_xor_sync(0xffffffffu, v, 16);
                    vs[si] = v;
                }
                float vsel = (dgrp == 0) ? vs[0]
                           : (dgrp == 1) ? vs[1]
                           : (dgrp == 2) ? vs[2] : vs[3];
                p_sm[(qbA + j) * TS + sown] = mk ? __expf(vsel) : 0.0f;
            }
        }
        __syncthreads();

        // ---- row-sums of p into l (144 threads, smem atomics) ----
        if (t < kNQ * 8) {
            int q = t >> 3, w8 = t & 7;
            const float4* pr = reinterpret_cast<const float4*>(p_sm + q * TS + w8 * 16);
            float ss = 0.0f;
            #pragma unroll
            for (int k2 = 0; k2 < 4; ++k2) {
                float4 v = pr[k2];
                ss += (v.x + v.y) + (v.z + v.w);
            }
            atomicAdd(&l_sm[q], ss);
        }

        // ================= phase B =================
        {
            const ulonglong2* xt =
                reinterpret_cast<const ulonglong2*>(xb4 + buf * XBUF_F4);
            #pragma unroll
            for (int i = 0; i < 8; ++i) {
                const int s0 = slB * 32 + i * 4;
                ulonglong2 xq[4];
                #pragma unroll
                for (int k2 = 0; k2 < 4; ++k2)
                    xq[k2] = xt[(s0 + k2) * 32 + ((d4B + s0 + k2) & 31)];
                #pragma unroll
                for (int j = 0; j < 9; ++j) {
                    float4 pv = reinterpret_cast<const float4*>(
                        p_sm + (qbB + j) * TS)[slB * 8 + i];
                    unsigned long long p0 = pk2(pv.x, pv.x);
                    acc[j][0] = f2ma(xq[0].x, p0, acc[j][0]);
                    acc[j][1] = f2ma(xq[0].y, p0, acc[j][1]);
                    unsigned long long p1 = pk2(pv.y, pv.y);
                    acc[j][0] = f2ma(xq[1].x, p1, acc[j][0]);
                    acc[j][1] = f2ma(xq[1].y, p1, acc[j][1]);
                    unsigned long long p2 = pk2(pv.z, pv.z);
                    acc[j][0] = f2ma(xq[2].x, p2, acc[j][0]);
                    acc[j][1] = f2ma(xq[2].y, p2, acc[j][1]);
                    unsigned long long p3 = pk2(pv.w, pv.w);
                    acc[j][0] = f2ma(xq[3].x, p3, acc[j][0]);
                    acc[j][1] = f2ma(xq[3].y, p3, acc[j][1]);
                }
            }
        }
        __syncthreads();
    }

    // ---- reduce 4 s-slices x 2 q-halves through smem (reuse x area) ----
    float* red = reinterpret_cast<float*>(smem);   // 4*18*128*4 = 36864 B
    #pragma unroll
    for (int j = 0; j < 9; ++j) {
        float2 a = up2(acc[j][0]);
        float2 c = up2(acc[j][1]);
        reinterpret_cast<float4*>(red)[(slB * kNQ + (qbB + j)) * 32 + d4B] =
            make_float4(a.x, a.y, c.x, c.y);
    }
    __syncthreads();

    float* ob = out + (size_t)b * OUT_PER_B;
    for (int o = t; o < OUT_PER_B; o += THREADS) {
        int q = o >> 7;
        float ssum = 0.0f;
        #pragma unroll
        for (int r = 0; r < 4; ++r) ssum += red[r * OUT_PER_B + o];
        ob[o] = ssum / l_sm[q];
    }
}

extern "C" void kernel_launch(void* const* d_in, const int* in_sizes, int n_in,
                              void* d_out, int out_size) {
    const float* x    = (const float*)d_in[0];
    const float* qe   = (const float*)d_in[1];
    const int*   ques = (const int*)d_in[2];
    const int*   mask = (const int*)d_in[3];
    float* out = (float*)d_out;

    cudaFuncSetAttribute(AttentionPooling_main,
                         cudaFuncAttributeMaxDynamicSharedMemorySize, SMEM_BYTES);
    AttentionPooling_main<<<kB, THREADS, SMEM_BYTES>>>(x, qe, ques, mask, out);
}